// round 1
// baseline (speedup 1.0000x reference)
#include <cuda_runtime.h>

typedef unsigned long long ull;

#define N_SAMP   16
#define L_DIM    128
#define D_DIM    128
#define H_HEADS  8
#define C_HEAD   16
#define HC       128
#define PAIRS    16384          // L*L
#define TOT_ROWS 262144         // N*L*L
#define SPITCH   132            // padded pitch for q/k/v/g tiles in kernel_attn

// Scratch (device globals: allocation-free per harness rules). 4 x 128MB.
__device__ float g_q[(long long)TOT_ROWS * HC];
__device__ float g_k[(long long)TOT_ROWS * HC];
__device__ float g_v[(long long)TOT_ROWS * HC];
__device__ float g_g[(long long)TOT_ROWS * HC];

// ---------- packed f32x2 helpers (B300: 2x fp32 FMA throughput, PTX-only) ----------
__device__ __forceinline__ ull pack2(float lo, float hi) {
    ull r; asm("mov.b64 %0, {%1, %2};" : "=l"(r) : "f"(lo), "f"(hi)); return r;
}
__device__ __forceinline__ void fma2(ull &d, ull a, ull b) {
    asm("fma.rn.f32x2 %0, %1, %2, %0;" : "+l"(d) : "l"(a), "l"(b));
}
__device__ __forceinline__ float2 unpack2(ull v) {
    float2 r; asm("mov.b64 {%0, %1}, %2;" : "=f"(r.x), "=f"(r.y) : "l"(v)); return r;
}
__device__ __forceinline__ float getc(const float4 &v, int kk) {
    switch (kk & 3) { case 0: return v.x; case 1: return v.y; case 2: return v.z; default: return v.w; }
}
__device__ __forceinline__ float sigmoidf_(float x) { return 1.0f / (1.0f + __expf(-x)); }

// =====================================================================================
// Kernel A: LayerNorm + 4 projections (q, k, v, g=sigmoid(zn@Wg+bg))
// One CTA = 128 rows. smem: znR[128][128] + Wsh[128][128] = 128KB.
// =====================================================================================
__global__ __launch_bounds__(512, 1)
void kernel_proj(const float* __restrict__ z,
                 const float* __restrict__ lnw, const float* __restrict__ lnb,
                 const float* __restrict__ Wq, const float* __restrict__ Wk,
                 const float* __restrict__ Wv, const float* __restrict__ Wg,
                 const float* __restrict__ bg)
{
    extern __shared__ float sm[];
    float* znR = sm;             // 128*128
    float* Wsh = sm + 16384;     // 128*128

    const int t    = threadIdx.x;
    const int lane = t & 31;
    const int warp = t >> 5;
    const long long r0 = (long long)blockIdx.x * 128;

    const float4 lw = *(const float4*)&lnw[lane * 4];
    const float4 lb = *(const float4*)&lnb[lane * 4];

    // LayerNorm: one warp per row, lane holds 4 channels
    for (int r = warp; r < 128; r += 16) {
        const float4 zv = *(const float4*)&z[(r0 + r) * 128 + lane * 4];
        float s  = zv.x + zv.y + zv.z + zv.w;
        float s2 = zv.x*zv.x + zv.y*zv.y + zv.z*zv.z + zv.w*zv.w;
        #pragma unroll
        for (int off = 16; off > 0; off >>= 1) {
            s  += __shfl_xor_sync(0xffffffffu, s,  off);
            s2 += __shfl_xor_sync(0xffffffffu, s2, off);
        }
        const float mu   = s * (1.0f / 128.0f);
        const float var  = s2 * (1.0f / 128.0f) - mu * mu;
        const float rstd = rsqrtf(var + 1e-5f);
        float4 o;
        o.x = (zv.x - mu) * rstd * lw.x + lb.x;
        o.y = (zv.y - mu) * rstd * lw.y + lb.y;
        o.z = (zv.z - mu) * rstd * lw.z + lb.z;
        o.w = (zv.w - mu) * rstd * lw.w + lb.w;
        *(float4*)&znR[r * 128 + lane * 4] = o;
    }
    __syncthreads();

    const float* Ws[4]   = {Wq, Wk, Wv, Wg};
    float* const outs[4] = {g_q, g_k, g_v, g_g};

    const int tx = t & 15;   // 16 col-tiles of 8
    const int ty = t >> 4;   // 32 row-tiles of 4

    for (int wsel = 0; wsel < 4; ++wsel) {
        // Stage W into smem
        {
            const float4* wg4 = (const float4*)Ws[wsel];
            float4* wsh4 = (float4*)Wsh;
            for (int idx = t; idx < 4096; idx += 512) wsh4[idx] = wg4[idx];
        }
        __syncthreads();

        ull acc[4][4];
        #pragma unroll
        for (int i = 0; i < 4; ++i)
            #pragma unroll
            for (int j = 0; j < 4; ++j) acc[i][j] = 0ull;

        for (int k = 0; k < 128; k += 4) {
            float4 a4[4];
            #pragma unroll
            for (int i = 0; i < 4; ++i)
                a4[i] = *(const float4*)&znR[(ty * 4 + i) * 128 + k];
            #pragma unroll
            for (int kk = 0; kk < 4; ++kk) {
                const ulonglong2 b0 = *(const ulonglong2*)&Wsh[(k + kk) * 128 + tx * 8];
                const ulonglong2 b1 = *(const ulonglong2*)&Wsh[(k + kk) * 128 + tx * 8 + 4];
                #pragma unroll
                for (int i = 0; i < 4; ++i) {
                    const float a = getc(a4[i], kk);
                    const ull aa = pack2(a, a);
                    fma2(acc[i][0], aa, b0.x);
                    fma2(acc[i][1], aa, b0.y);
                    fma2(acc[i][2], aa, b1.x);
                    fma2(acc[i][3], aa, b1.y);
                }
            }
        }

        float* dst = outs[wsel];
        float4 bga = make_float4(0.f, 0.f, 0.f, 0.f);
        float4 bgb = make_float4(0.f, 0.f, 0.f, 0.f);
        if (wsel == 3) {
            bga = *(const float4*)&bg[tx * 8];
            bgb = *(const float4*)&bg[tx * 8 + 4];
        }
        #pragma unroll
        for (int i = 0; i < 4; ++i) {
            const int row = ty * 4 + i;
            float2 p0 = unpack2(acc[i][0]);
            float2 p1 = unpack2(acc[i][1]);
            float2 p2 = unpack2(acc[i][2]);
            float2 p3 = unpack2(acc[i][3]);
            if (wsel == 3) {
                p0.x = sigmoidf_(p0.x + bga.x); p0.y = sigmoidf_(p0.y + bga.y);
                p1.x = sigmoidf_(p1.x + bga.z); p1.y = sigmoidf_(p1.y + bga.w);
                p2.x = sigmoidf_(p2.x + bgb.x); p2.y = sigmoidf_(p2.y + bgb.y);
                p3.x = sigmoidf_(p3.x + bgb.z); p3.y = sigmoidf_(p3.y + bgb.w);
            }
            *(float4*)&dst[(r0 + row) * 128 + tx * 8]     = make_float4(p0.x, p0.y, p1.x, p1.y);
            *(float4*)&dst[(r0 + row) * 128 + tx * 8 + 4] = make_float4(p2.x, p2.y, p3.x, p3.y);
        }
        __syncthreads();  // before Wsh is overwritten
    }
}

// =====================================================================================
// Kernel B: per-pair attention over sample axis + gating + output GEMM (@Wo + bo)
// One CTA = 8 (a,b) pairs. smem: 4x q/k/v/g[16][132] + att[2048] + so[128][128] + Wo[128][128]
// =====================================================================================
__global__ __launch_bounds__(512, 1)
void kernel_attn(const float* __restrict__ Wo, const float* __restrict__ bo,
                 float* __restrict__ out)
{
    extern __shared__ float sm[];
    float* sq  = sm;                        // 16*132 each, tensors contiguous
    float* sk  = sq + 16 * SPITCH;
    float* sv  = sk + 16 * SPITCH;
    float* sg  = sv + 16 * SPITCH;
    float* att = sg + 16 * SPITCH;          // 8*16*16 = 2048
    float* so  = att + 2048;                // 128*128
    float* Wsh = so + 16384;                // 128*128

    const int t     = threadIdx.x;
    const int lane  = t & 31;
    const int warp  = t >> 5;
    const int pbase = blockIdx.x * 8;

    // Stage Wo (read only after the pair loop's final sync)
    {
        const float4* wg4 = (const float4*)Wo;
        float4* wsh4 = (float4*)Wsh;
        for (int idx = t; idx < 4096; idx += 512) wsh4[idx] = wg4[idx];
    }

    const float* bases[4] = {g_q, g_k, g_v, g_g};

    for (int pl = 0; pl < 8; ++pl) {
        const int p = pbase + pl;
        __syncthreads();  // previous pair fully consumed before overwrite

        // Load q/k/v/g rows (16 samples x 128) for this pair
        for (int rt = warp; rt < 64; rt += 16) {
            const int tensor = rt >> 4;
            const int i      = rt & 15;
            const float4* src = (const float4*)&bases[tensor][((long long)i * PAIRS + p) * 128];
            float4* dst = (float4*)&sm[tensor * (16 * SPITCH) + i * SPITCH];
            dst[lane] = src[lane];
        }
        __syncthreads();

        // att[h][i][j] = 0.25 * sum_c q[i,h,c] k[j,h,c]
        for (int e = t; e < 2048; e += 512) {
            const int h = e >> 8;
            const int i = (e >> 4) & 15;
            const int j = e & 15;
            const float* qa = &sq[i * SPITCH + h * 16];
            const float* ka = &sk[j * SPITCH + h * 16];
            float s = 0.f;
            #pragma unroll
            for (int c = 0; c < 16; ++c) s += qa[c] * ka[c];
            att[e] = s * 0.25f;
        }
        __syncthreads();

        // softmax over j for each (h,i)
        if (t < 128) {
            float* ar = &att[t * 16];
            float m = ar[0];
            #pragma unroll
            for (int j = 1; j < 16; ++j) m = fmaxf(m, ar[j]);
            float s = 0.f;
            #pragma unroll
            for (int j = 0; j < 16; ++j) { float e_ = __expf(ar[j] - m); ar[j] = e_; s += e_; }
            const float inv = 1.0f / s;
            #pragma unroll
            for (int j = 0; j < 16; ++j) ar[j] *= inv;
        }
        __syncthreads();

        // o[i][hc] = (sum_j att * v[j][hc]) * g[i][hc], stored into so tile
        for (int e = t; e < 2048; e += 512) {
            const int i  = e >> 7;
            const int hc = e & 127;
            const int h  = hc >> 4;
            const float* ar = &att[(h * 16 + i) * 16];
            float s = 0.f;
            #pragma unroll
            for (int j = 0; j < 16; ++j) s += ar[j] * sv[j * SPITCH + hc];
            so[(pl * 16 + i) * 128 + hc] = s * sg[i * SPITCH + hc];
        }
    }
    __syncthreads();

    // out = so(128x128) @ Wo + bo
    const int tx = t & 15;
    const int ty = t >> 4;
    ull acc[4][4];
    #pragma unroll
    for (int i = 0; i < 4; ++i)
        #pragma unroll
        for (int j = 0; j < 4; ++j) acc[i][j] = 0ull;

    for (int k = 0; k < 128; k += 4) {
        float4 a4[4];
        #pragma unroll
        for (int i = 0; i < 4; ++i)
            a4[i] = *(const float4*)&so[(ty * 4 + i) * 128 + k];
        #pragma unroll
        for (int kk = 0; kk < 4; ++kk) {
            const ulonglong2 b0 = *(const ulonglong2*)&Wsh[(k + kk) * 128 + tx * 8];
            const ulonglong2 b1 = *(const ulonglong2*)&Wsh[(k + kk) * 128 + tx * 8 + 4];
            #pragma unroll
            for (int i = 0; i < 4; ++i) {
                const float a = getc(a4[i], kk);
                const ull aa = pack2(a, a);
                fma2(acc[i][0], aa, b0.x);
                fma2(acc[i][1], aa, b0.y);
                fma2(acc[i][2], aa, b1.x);
                fma2(acc[i][3], aa, b1.y);
            }
        }
    }

    const float4 boa = *(const float4*)&bo[tx * 8];
    const float4 bob = *(const float4*)&bo[tx * 8 + 4];
    #pragma unroll
    for (int i = 0; i < 4; ++i) {
        const int rr = ty * 4 + i;
        const int ii = rr & 15;        // sample index
        const int pl = rr >> 4;        // pair-local index
        float2 p0 = unpack2(acc[i][0]);
        float2 p1 = unpack2(acc[i][1]);
        float2 p2 = unpack2(acc[i][2]);
        float2 p3 = unpack2(acc[i][3]);
        float* dst = &out[((long long)ii * PAIRS + (pbase + pl)) * 128 + tx * 8];
        *(float4*)&dst[0] = make_float4(p0.x + boa.x, p0.y + boa.y, p1.x + boa.z, p1.y + boa.w);
        *(float4*)&dst[4] = make_float4(p2.x + bob.x, p2.y + bob.y, p3.x + bob.z, p3.y + bob.w);
    }
}

// =====================================================================================
extern "C" void kernel_launch(void* const* d_in, const int* in_sizes, int n_in,
                              void* d_out, int out_size)
{
    (void)in_sizes; (void)n_in; (void)out_size;
    const float* z   = (const float*)d_in[0];
    const float* lnw = (const float*)d_in[1];
    const float* lnb = (const float*)d_in[2];
    const float* Wq  = (const float*)d_in[3];
    const float* Wk  = (const float*)d_in[4];
    const float* Wv  = (const float*)d_in[5];
    const float* Wg  = (const float*)d_in[6];
    const float* bg  = (const float*)d_in[7];
    const float* Wo  = (const float*)d_in[8];
    const float* bo  = (const float*)d_in[9];
    float* out = (float*)d_out;

    const int smemA = 2 * 16384 * (int)sizeof(float);                       // 131072 B
    const int smemB = (4 * 16 * SPITCH + 2048 + 16384 + 16384) * (int)sizeof(float); // 173056 B
    cudaFuncSetAttribute(kernel_proj, cudaFuncAttributeMaxDynamicSharedMemorySize, smemA);
    cudaFuncSetAttribute(kernel_attn, cudaFuncAttributeMaxDynamicSharedMemorySize, smemB);

    kernel_proj<<<2048, 512, smemA>>>(z, lnw, lnb, Wq, Wk, Wv, Wg, bg);
    kernel_attn<<<2048, 512, smemB>>>(Wo, bo, out);
}

// round 3
// speedup vs baseline: 2.4436x; 2.4436x over previous
#include <cuda_runtime.h>
#include <cuda_bf16.h>
#include <cstdint>

typedef unsigned long long ull;

#define HC       128
#define PAIRS    16384          // L*L
#define TOT_ROWS 262144         // N*L*L
#define SPITCH   132

// ---------------- device scratch ----------------
__device__ float g_q[(long long)TOT_ROWS * HC];
__device__ float g_k[(long long)TOT_ROWS * HC];
__device__ float g_v[(long long)TOT_ROWS * HC];
__device__ float g_g[(long long)TOT_ROWS * HC];
__device__ float g_o[(long long)TOT_ROWS * HC];
// W images: 5 matrices (Wq,Wk,Wv,Wg,Wo), each [hi 128x128][lo 128x128] bf16, [n][k] layout
__device__ __nv_bfloat16 g_wimg[5 * 2 * 16384];

// ---------------- helpers ----------------
__device__ __forceinline__ uint32_t smem_u32(const void* p) {
    uint32_t a;
    asm("{ .reg .u64 t; cvta.to.shared.u64 t, %1; cvt.u32.u64 %0, t; }" : "=r"(a) : "l"(p));
    return a;
}
__device__ __forceinline__ float sigmoidf_(float x) { return 1.0f / (1.0f + __expf(-x)); }

__device__ __forceinline__ void ldmA(uint32_t r[4], uint32_t addr) {
    asm volatile("ldmatrix.sync.aligned.m8n8.x4.shared.b16 {%0,%1,%2,%3}, [%4];"
                 : "=r"(r[0]), "=r"(r[1]), "=r"(r[2]), "=r"(r[3]) : "r"(addr));
}
__device__ __forceinline__ void ldmB(uint32_t r[2], uint32_t addr) {
    asm volatile("ldmatrix.sync.aligned.m8n8.x2.shared.b16 {%0,%1}, [%2];"
                 : "=r"(r[0]), "=r"(r[1]) : "r"(addr));
}
__device__ __forceinline__ void mma_bf16(float c[4], const uint32_t a[4], const uint32_t b[2]) {
    asm volatile(
        "mma.sync.aligned.m16n8k16.row.col.f32.bf16.bf16.f32 "
        "{%0,%1,%2,%3}, {%4,%5,%6,%7}, {%8,%9}, {%0,%1,%2,%3};"
        : "+f"(c[0]), "+f"(c[1]), "+f"(c[2]), "+f"(c[3])
        : "r"(a[0]), "r"(a[1]), "r"(a[2]), "r"(a[3]), "r"(b[0]), "r"(b[1]));
}
__device__ __forceinline__ void cp_async16(uint32_t dst, const void* src) {
    asm volatile("cp.async.ca.shared.global [%0], [%1], 16;" :: "r"(dst), "l"(src));
}
__device__ __forceinline__ void cp_commit() { asm volatile("cp.async.commit_group;"); }

// smem tile pitch: 136 bf16 = 272 bytes (16B aligned for ldmatrix)
#define APITCH 136
#define TILE_B (128 * APITCH * 2)        // 34816 bytes per 128x128 bf16 tile
// proj smem: A_hi, A_lo, B0_hi, B0_lo, B1_hi, B1_lo
#define OFF_AHI 0u
#define OFF_ALO (OFF_AHI + TILE_B)
#define OFF_B0H (OFF_ALO + TILE_B)
#define OFF_B0L (OFF_B0H + TILE_B)
#define OFF_B1H (OFF_B0L + TILE_B)
#define OFF_B1L (OFF_B1H + TILE_B)
#define SMEM_PROJ (OFF_B1L + TILE_B)     // 208896 B
#define SMEM_OUT  (OFF_B0L + TILE_B)     // 139264 B

// =====================================================================================
// prep: split W into bf16 hi/lo, transpose to [n][k]
// =====================================================================================
__global__ void kernel_prep(const float* __restrict__ Wq, const float* __restrict__ Wk,
                            const float* __restrict__ Wv, const float* __restrict__ Wg,
                            const float* __restrict__ Wo)
{
    const int m = blockIdx.x;  // 0..4
    const float* W = (m == 0) ? Wq : (m == 1) ? Wk : (m == 2) ? Wv : (m == 3) ? Wg : Wo;
    __nv_bfloat16* hi = g_wimg + (long long)m * 32768;
    __nv_bfloat16* lo = hi + 16384;
    for (int idx = threadIdx.x; idx < 16384; idx += blockDim.x) {
        const int n = idx >> 7, k = idx & 127;
        const float x = W[k * 128 + n];
        const __nv_bfloat16 h = __float2bfloat16_rn(x);
        hi[n * 128 + k] = h;
        lo[n * 128 + k] = __float2bfloat16_rn(x - __bfloat162float(h));
    }
}

// ---------------- shared GEMM pieces ----------------
// split float4 -> hi/lo bf16x4, store 8B each at element offset (row*APITCH + c0)
__device__ __forceinline__ void split_store(char* smem, uint32_t offHi, uint32_t offLo,
                                            int row, int c0, float4 v)
{
    __nv_bfloat162 h01, h23, l01, l23;
    const __nv_bfloat16 hx = __float2bfloat16_rn(v.x), hy = __float2bfloat16_rn(v.y);
    const __nv_bfloat16 hz = __float2bfloat16_rn(v.z), hw = __float2bfloat16_rn(v.w);
    h01.x = hx; h01.y = hy; h23.x = hz; h23.y = hw;
    l01.x = __float2bfloat16_rn(v.x - __bfloat162float(hx));
    l01.y = __float2bfloat16_rn(v.y - __bfloat162float(hy));
    l23.x = __float2bfloat16_rn(v.z - __bfloat162float(hz));
    l23.y = __float2bfloat16_rn(v.w - __bfloat162float(hw));
    const uint32_t byteOff = (uint32_t)(row * APITCH + c0) * 2u;
    *(__nv_bfloat162*)(smem + offHi + byteOff)     = h01;
    *(__nv_bfloat162*)(smem + offHi + byteOff + 4) = h23;
    *(__nv_bfloat162*)(smem + offLo + byteOff)     = l01;
    *(__nv_bfloat162*)(smem + offLo + byteOff + 4) = l23;
}

// issue cp.async staging of one W image (hi+lo) into smem B buffer
__device__ __forceinline__ void stage_B(char* smem, uint32_t offH, uint32_t offL,
                                        const __nv_bfloat16* img, int t)
{
    const uint32_t base = smem_u32(smem);
    // hi: 2048 chunks of 16B, lo: 2048 chunks
    for (int idx = t; idx < 4096; idx += 512) {
        const int half = idx >> 11;            // 0 = hi, 1 = lo
        const int e    = idx & 2047;
        const int row  = e >> 4, c = e & 15;
        const uint32_t dst = base + (half ? offL : offH) + (uint32_t)(row * APITCH * 2 + c * 16);
        cp_async16(dst, img + (long long)half * 16384 + row * 128 + c * 8);
    }
}

// one warp-tile GEMM over the staged buffers: C(32x32) = A(128x128) x B^T slice
// warp wm,wn; fragments via ldmatrix; 3-term bf16 emulation
__device__ __forceinline__ void warp_gemm(char* smem, uint32_t offBH, uint32_t offBL,
                                          int wm, int wn, int lane, float c[2][4][4])
{
    const uint32_t base = smem_u32(smem);
    const uint32_t aOff = base + (uint32_t)((wm * 32 + (lane & 15)) * APITCH * 2 + (lane >> 4) * 16);
    const uint32_t bOff = base + (uint32_t)((wn * 32 + (lane & 7)) * APITCH * 2 + ((lane >> 3) & 1) * 16);
    #pragma unroll
    for (int mb = 0; mb < 2; ++mb)
        #pragma unroll
        for (int nb = 0; nb < 4; ++nb)
            #pragma unroll
            for (int q = 0; q < 4; ++q) c[mb][nb][q] = 0.0f;

    #pragma unroll
    for (int k = 0; k < 8; ++k) {
        uint32_t ah[2][4], al[2][4], bh[4][2], bl[4][2];
        #pragma unroll
        for (int mb = 0; mb < 2; ++mb) {
            ldmA(ah[mb], aOff + OFF_AHI + (uint32_t)(mb * 16 * APITCH * 2 + k * 32));
            ldmA(al[mb], aOff + OFF_ALO + (uint32_t)(mb * 16 * APITCH * 2 + k * 32));
        }
        #pragma unroll
        for (int nb = 0; nb < 4; ++nb) {
            ldmB(bh[nb], bOff + offBH + (uint32_t)(nb * 8 * APITCH * 2 + k * 32));
            ldmB(bl[nb], bOff + offBL + (uint32_t)(nb * 8 * APITCH * 2 + k * 32));
        }
        #pragma unroll
        for (int mb = 0; mb < 2; ++mb)
            #pragma unroll
            for (int nb = 0; nb < 4; ++nb) {
                mma_bf16(c[mb][nb], ah[mb], bh[nb]);
                mma_bf16(c[mb][nb], ah[mb], bl[nb]);
                mma_bf16(c[mb][nb], al[mb], bh[nb]);
            }
    }
}

// =====================================================================================
// proj: LN + 4 projections (q,k,v,g) via HMMA bf16x3, B double-buffered with cp.async
// =====================================================================================
__global__ __launch_bounds__(512, 1)
void kernel_proj(const float* __restrict__ z,
                 const float* __restrict__ lnw, const float* __restrict__ lnb,
                 const float* __restrict__ bg)
{
    extern __shared__ char smem[];
    const int t = threadIdx.x, lane = t & 31, warp = t >> 5;
    const int wm = warp >> 2, wn = warp & 3;
    const long long r0 = (long long)blockIdx.x * 128;

    const float4 lw = *(const float4*)&lnw[lane * 4];
    const float4 lb = *(const float4*)&lnb[lane * 4];

    // LayerNorm -> split A into smem
    for (int r = warp; r < 128; r += 16) {
        const float4 zv = *(const float4*)&z[(r0 + r) * 128 + lane * 4];
        float s  = zv.x + zv.y + zv.z + zv.w;
        float s2 = zv.x*zv.x + zv.y*zv.y + zv.z*zv.z + zv.w*zv.w;
        #pragma unroll
        for (int off = 16; off > 0; off >>= 1) {
            s  += __shfl_xor_sync(0xffffffffu, s,  off);
            s2 += __shfl_xor_sync(0xffffffffu, s2, off);
        }
        const float mu   = s * (1.0f / 128.0f);
        const float var  = s2 * (1.0f / 128.0f) - mu * mu;
        const float rstd = rsqrtf(var + 1e-5f);
        float4 o;
        o.x = (zv.x - mu) * rstd * lw.x + lb.x;
        o.y = (zv.y - mu) * rstd * lw.y + lb.y;
        o.z = (zv.z - mu) * rstd * lw.z + lb.z;
        o.w = (zv.w - mu) * rstd * lw.w + lb.w;
        split_store(smem, OFF_AHI, OFF_ALO, r, lane * 4, o);
    }

    // prefetch W0
    stage_B(smem, OFF_B0H, OFF_B0L, g_wimg, t);
    cp_commit();

    float* const outs[4] = {g_q, g_k, g_v, g_g};

    for (int s = 0; s < 4; ++s) {
        const uint32_t offH = (s & 1) ? OFF_B1H : OFF_B0H;
        const uint32_t offL = (s & 1) ? OFF_B1L : OFF_B0L;
        if (s < 3) {
            stage_B(smem, (s & 1) ? OFF_B0H : OFF_B1H, (s & 1) ? OFF_B0L : OFF_B1L,
                    g_wimg + (long long)(s + 1) * 32768, t);
            cp_commit();
            asm volatile("cp.async.wait_group 1;");
        } else {
            asm volatile("cp.async.wait_group 0;");
        }
        __syncthreads();

        float c[2][4][4];
        warp_gemm(smem, offH, offL, wm, wn, lane, c);

        // epilogue: direct stores
        float* dst = outs[s];
        #pragma unroll
        for (int mb = 0; mb < 2; ++mb) {
            const long long grow = r0 + wm * 32 + mb * 16 + (lane >> 2);
            #pragma unroll
            for (int nb = 0; nb < 4; ++nb) {
                const int col = wn * 32 + nb * 8 + 2 * (lane & 3);
                float v0 = c[mb][nb][0], v1 = c[mb][nb][1];
                float v2 = c[mb][nb][2], v3 = c[mb][nb][3];
                if (s == 3) {
                    const float b0 = bg[col], b1 = bg[col + 1];
                    v0 = sigmoidf_(v0 + b0); v1 = sigmoidf_(v1 + b1);
                    v2 = sigmoidf_(v2 + b0); v3 = sigmoidf_(v3 + b1);
                }
                *(float2*)&dst[grow * 128 + col]       = make_float2(v0, v1);
                *(float2*)&dst[(grow + 8) * 128 + col] = make_float2(v2, v3);
            }
        }
        __syncthreads();   // buffer reuse fence before next stage overwrite
    }
}

// =====================================================================================
// attn: per-pair 16-sample attention + gating, register-blocked, 2 CTAs/SM
// =====================================================================================
__global__ __launch_bounds__(512, 2)
void kernel_attn()
{
    __shared__ float smA[4 * 16 * SPITCH + 2048];
    float* sq  = smA;
    float* sk  = sq + 16 * SPITCH;
    float* sv  = sk + 16 * SPITCH;
    float* sg  = sv + 16 * SPITCH;
    float* att = sg + 16 * SPITCH;

    const int t = threadIdx.x, lane = t & 31, warp = t >> 5;
    const int pbase = blockIdx.x * 8;
    const float* bases[4] = {g_q, g_k, g_v, g_g};

    for (int pl = 0; pl < 8; ++pl) {
        const int p = pbase + pl;
        if (pl > 0) __syncthreads();

        for (int rt = warp; rt < 64; rt += 16) {
            const int tensor = rt >> 4;
            const int i      = rt & 15;
            const float4* src = (const float4*)&bases[tensor][((long long)i * PAIRS + p) * 128];
            float4* dstp = (float4*)&smA[tensor * (16 * SPITCH) + i * SPITCH];
            dstp[lane] = src[lane];
        }
        __syncthreads();

        // QK^T: 2x2 register blocking, one quad per thread
        {
            const int h  = t >> 6;
            const int i0 = ((t >> 3) & 7) * 2;
            const int j0 = (t & 7) * 2;
            const float4* qa0 = (const float4*)&sq[i0 * SPITCH + h * 16];
            const float4* qa1 = (const float4*)&sq[(i0 + 1) * SPITCH + h * 16];
            const float4* ka0 = (const float4*)&sk[j0 * SPITCH + h * 16];
            const float4* ka1 = (const float4*)&sk[(j0 + 1) * SPITCH + h * 16];
            float s00 = 0.f, s01 = 0.f, s10 = 0.f, s11 = 0.f;
            #pragma unroll
            for (int c4 = 0; c4 < 4; ++c4) {
                const float4 q0 = qa0[c4], q1 = qa1[c4], k0 = ka0[c4], k1 = ka1[c4];
                s00 += q0.x*k0.x + q0.y*k0.y + q0.z*k0.z + q0.w*k0.w;
                s01 += q0.x*k1.x + q0.y*k1.y + q0.z*k1.z + q0.w*k1.w;
                s10 += q1.x*k0.x + q1.y*k0.y + q1.z*k0.z + q1.w*k0.w;
                s11 += q1.x*k1.x + q1.y*k1.y + q1.z*k1.z + q1.w*k1.w;
            }
            float* ab = &att[h * 256 + i0 * 16 + j0];
            ab[0] = s00 * 0.25f; ab[1] = s01 * 0.25f;
            ab[16] = s10 * 0.25f; ab[17] = s11 * 0.25f;
        }
        __syncthreads();

        if (t < 128) {
            float* ar = &att[t * 16];
            float m = ar[0];
            #pragma unroll
            for (int j = 1; j < 16; ++j) m = fmaxf(m, ar[j]);
            float s = 0.f;
            #pragma unroll
            for (int j = 0; j < 16; ++j) { float e_ = __expf(ar[j] - m); ar[j] = e_; s += e_; }
            const float inv = 1.0f / s;
            #pragma unroll
            for (int j = 0; j < 16; ++j) ar[j] *= inv;
        }
        __syncthreads();

        // att @ V with gating: 2i x 2hc per thread
        {
            const int i0  = (t >> 6) * 2;
            const int hc0 = (t & 63) * 2;
            const int h   = hc0 >> 4;
            const float* ar0 = &att[(h * 16 + i0) * 16];
            const float* ar1 = ar0 + 16;
            float a0x = 0.f, a0y = 0.f, a1x = 0.f, a1y = 0.f;
            #pragma unroll
            for (int j = 0; j < 16; ++j) {
                const float2 vv = *(const float2*)&sv[j * SPITCH + hc0];
                const float w0 = ar0[j], w1 = ar1[j];
                a0x += w0 * vv.x; a0y += w0 * vv.y;
                a1x += w1 * vv.x; a1y += w1 * vv.y;
            }
            const float2 gg0 = *(const float2*)&sg[i0 * SPITCH + hc0];
            const float2 gg1 = *(const float2*)&sg[(i0 + 1) * SPITCH + hc0];
            *(float2*)&g_o[((long long)i0 * PAIRS + p) * 128 + hc0] =
                make_float2(a0x * gg0.x, a0y * gg0.y);
            *(float2*)&g_o[((long long)(i0 + 1) * PAIRS + p) * 128 + hc0] =
                make_float2(a1x * gg1.x, a1y * gg1.y);
        }
    }
}

// =====================================================================================
// out: o @ Wo + bo via HMMA bf16x3
// =====================================================================================
__global__ __launch_bounds__(512, 1)
void kernel_out(const float* __restrict__ bo, float* __restrict__ out)
{
    extern __shared__ char smem[];
    const int t = threadIdx.x, lane = t & 31, warp = t >> 5;
    const int wm = warp >> 2, wn = warp & 3;
    const long long r0 = (long long)blockIdx.x * 128;

    stage_B(smem, OFF_B0H, OFF_B0L, g_wimg + 4ll * 32768, t);
    cp_commit();

    for (int r = warp; r < 128; r += 16) {
        const float4 v = *(const float4*)&g_o[(r0 + r) * 128 + lane * 4];
        split_store(smem, OFF_AHI, OFF_ALO, r, lane * 4, v);
    }
    asm volatile("cp.async.wait_group 0;");
    __syncthreads();

    float c[2][4][4];
    warp_gemm(smem, OFF_B0H, OFF_B0L, wm, wn, lane, c);

    #pragma unroll
    for (int mb = 0; mb < 2; ++mb) {
        const long long grow = r0 + wm * 32 + mb * 16 + (lane >> 2);
        #pragma unroll
        for (int nb = 0; nb < 4; ++nb) {
            const int col = wn * 32 + nb * 8 + 2 * (lane & 3);
            const float b0 = bo[col], b1 = bo[col + 1];
            *(float2*)&out[grow * 128 + col] =
                make_float2(c[mb][nb][0] + b0, c[mb][nb][1] + b1);
            *(float2*)&out[(grow + 8) * 128 + col] =
                make_float2(c[mb][nb][2] + b0, c[mb][nb][3] + b1);
        }
    }
}

// =====================================================================================
extern "C" void kernel_launch(void* const* d_in, const int* in_sizes, int n_in,
                              void* d_out, int out_size)
{
    (void)in_sizes; (void)n_in; (void)out_size;
    const float* z   = (const float*)d_in[0];
    const float* lnw = (const float*)d_in[1];
    const float* lnb = (const float*)d_in[2];
    const float* Wq  = (const float*)d_in[3];
    const float* Wk  = (const float*)d_in[4];
    const float* Wv  = (const float*)d_in[5];
    const float* Wg  = (const float*)d_in[6];
    const float* bg  = (const float*)d_in[7];
    const float* Wo  = (const float*)d_in[8];
    const float* bo  = (const float*)d_in[9];
    float* out = (float*)d_out;

    cudaFuncSetAttribute(kernel_proj, cudaFuncAttributeMaxDynamicSharedMemorySize, SMEM_PROJ);
    cudaFuncSetAttribute(kernel_out,  cudaFuncAttributeMaxDynamicSharedMemorySize, SMEM_OUT);

    kernel_prep<<<5, 256>>>(Wq, Wk, Wv, Wg, Wo);
    kernel_proj<<<2048, 512, SMEM_PROJ>>>(z, lnw, lnb, bg);
    kernel_attn<<<2048, 512>>>();
    kernel_out<<<2048, 512, SMEM_OUT>>>(bo, out);
}